// round 1
// baseline (speedup 1.0000x reference)
#include <cuda_runtime.h>
#include <math.h>

// Shapes (fixed by the problem)
#define B_  16
#define C_  256
#define HIDE_ 128
#define HW_ 16384          // 128*128
#define HW4_ 4096          // float4 per row
#define ROWS_ (B_*C_)      // 4096

__device__ float g_mean[ROWS_];
__device__ float g_gate[ROWS_];

// ---------------- Kernel 1: per-(b,c) mean over H*W ----------------
__global__ void __launch_bounds__(256) k_reduce(const float* __restrict__ x) {
    int row = blockIdx.x;
    const float4* xr = reinterpret_cast<const float4*>(x) + (size_t)row * HW4_;
    float s = 0.f;
    #pragma unroll 4
    for (int i = threadIdx.x; i < HW4_; i += 256) {
        float4 v = xr[i];
        s += (v.x + v.y) + (v.z + v.w);
    }
    // warp reduce then smem reduce
    #pragma unroll
    for (int off = 16; off > 0; off >>= 1)
        s += __shfl_down_sync(0xffffffffu, s, off);
    __shared__ float sm[8];
    int lane = threadIdx.x & 31, wid = threadIdx.x >> 5;
    if (lane == 0) sm[wid] = s;
    __syncthreads();
    if (wid == 0) {
        s = (lane < 8) ? sm[lane] : 0.f;
        #pragma unroll
        for (int off = 4; off > 0; off >>= 1)
            s += __shfl_down_sync(0xffffffffu, s, off);
        if (lane == 0) g_mean[row] = s * (1.0f / (float)HW_);
    }
}

// ---------------- Kernel 2: gate computation (one block per batch) ----------------
__global__ void __launch_bounds__(256) k_gate(const float* __restrict__ w1,
                                              const float* __restrict__ w2p,
                                              const float* __restrict__ w3p,
                                              const float* __restrict__ w4,
                                              const float* __restrict__ A2) {
    int b = blockIdx.x;
    int t = threadIdx.x;
    __shared__ float mean_s[C_];
    __shared__ float y_s[HIDE_];
    __shared__ float z_s[HIDE_];
    __shared__ float red[256];

    mean_s[t] = g_mean[b * C_ + t];
    __syncthreads();

    const float w2 = *w2p;
    const float w3 = *w3p;

    // conv1: y[j] = dot(mean, w1[j,:])
    if (t < HIDE_) {
        float acc = 0.f;
        const float* wr = w1 + (size_t)t * C_;
        #pragma unroll 8
        for (int k = 0; k < C_; ++k) acc = fmaf(mean_s[k], wr[k], acc);
        y_s[t] = acc;
    }
    __syncthreads();

    // softmax over HIDE of (w2 * y)
    float v = (t < HIDE_) ? w2 * y_s[t] : -INFINITY;
    red[t] = v;
    __syncthreads();
    #pragma unroll
    for (int off = 128; off > 0; off >>= 1) {
        if (t < off) red[t] = fmaxf(red[t], red[t + off]);
        __syncthreads();
    }
    float m = red[0];
    __syncthreads();
    float e = (t < HIDE_) ? __expf(v - m) : 0.f;
    red[t] = e;
    __syncthreads();
    #pragma unroll
    for (int off = 128; off > 0; off >>= 1) {
        if (t < off) red[t] += red[t + off];
        __syncthreads();
    }
    float inv_sum = 1.0f / red[0];
    __syncthreads();

    // y2[j] = y[j]*softmax[j] + sum_k y[k]*A2[k,j]; z = relu(w3*y2)
    if (t < HIDE_) {
        float acc = 0.f;
        #pragma unroll 8
        for (int k = 0; k < HIDE_; ++k) acc = fmaf(y_s[k], A2[(size_t)k * HIDE_ + t], acc);
        float y2 = y_s[t] * (e * inv_sum) + acc;
        z_s[t] = fmaxf(w3 * y2, 0.f);
    }
    __syncthreads();

    // conv4 + sigmoid: gate[c] = sigmoid(dot(z, w4[c,:]))
    {
        float acc = 0.f;
        const float* wr = w4 + (size_t)t * HIDE_;
        #pragma unroll 8
        for (int k = 0; k < HIDE_; ++k) acc = fmaf(z_s[k], wr[k], acc);
        g_gate[b * C_ + t] = 1.0f / (1.0f + __expf(-acc));
    }
}

// ---------------- Kernel 3: out = x * gate (broadcast per row) ----------------
__global__ void __launch_bounds__(256) k_scale(const float* __restrict__ x,
                                               float* __restrict__ out) {
    size_t i = (size_t)blockIdx.x * 256 + threadIdx.x;   // float4 index
    const float4* x4 = reinterpret_cast<const float4*>(x);
    float4* o4 = reinterpret_cast<float4*>(out);
    int row = (int)(i >> 12);           // 4096 float4 per (b,c) row
    float g = g_gate[row];
    float4 v = x4[i];
    v.x *= g; v.y *= g; v.z *= g; v.w *= g;
    o4[i] = v;
}

extern "C" void kernel_launch(void* const* d_in, const int* in_sizes, int n_in,
                              void* d_out, int out_size) {
    const float* x  = (const float*)d_in[0];
    const float* w1 = (const float*)d_in[1];
    const float* w2 = (const float*)d_in[2];
    const float* w3 = (const float*)d_in[3];
    const float* w4 = (const float*)d_in[4];
    const float* A2 = (const float*)d_in[5];
    float* out = (float*)d_out;

    k_reduce<<<ROWS_, 256>>>(x);
    k_gate<<<B_, 256>>>(w1, w2, w3, w4, A2);
    // total float4 elements = 16*256*4096 = 16,777,216 -> 65536 blocks of 256
    k_scale<<<(ROWS_ * HW4_) / 256, 256>>>(x, out);
}

// round 2
// speedup vs baseline: 1.1619x; 1.1619x over previous
#include <cuda_runtime.h>
#include <math.h>

// Shapes (fixed by the problem)
#define B_  16
#define C_  256
#define HIDE_ 128
#define HW_ 16384          // 128*128
#define HW4_ 4096          // float4 per row
#define ROWS_ (B_*C_)      // 4096

__device__ float g_mean[ROWS_];
__device__ float g_gate[ROWS_];

// ---------------- Kernel 1: per-(b,c) mean over H*W ----------------
__global__ void __launch_bounds__(256) k_reduce(const float* __restrict__ x) {
    int row = blockIdx.x;
    const float4* xr = reinterpret_cast<const float4*>(x) + (size_t)row * HW4_;
    float s = 0.f;
    #pragma unroll 4
    for (int i = threadIdx.x; i < HW4_; i += 256) {
        float4 v = xr[i];
        s += (v.x + v.y) + (v.z + v.w);
    }
    #pragma unroll
    for (int off = 16; off > 0; off >>= 1)
        s += __shfl_down_sync(0xffffffffu, s, off);
    __shared__ float sm[8];
    int lane = threadIdx.x & 31, wid = threadIdx.x >> 5;
    if (lane == 0) sm[wid] = s;
    __syncthreads();
    if (wid == 0) {
        s = (lane < 8) ? sm[lane] : 0.f;
        #pragma unroll
        for (int off = 4; off > 0; off >>= 1)
            s += __shfl_down_sync(0xffffffffu, s, off);
        if (lane == 0) g_mean[row] = s * (1.0f / (float)HW_);
    }
}

// ---------------- Kernel 2: gate computation (one block per batch) ----------------
__global__ void __launch_bounds__(256) k_gate(const float* __restrict__ w1,
                                              const float* __restrict__ w2p,
                                              const float* __restrict__ w3p,
                                              const float* __restrict__ w4,
                                              const float* __restrict__ A2) {
    int b = blockIdx.x;
    int t = threadIdx.x;
    __shared__ float mean_s[C_];
    __shared__ float y_s[HIDE_];
    __shared__ float z_s[HIDE_];
    __shared__ float red[256];

    mean_s[t] = g_mean[b * C_ + t];
    __syncthreads();

    const float w2 = *w2p;
    const float w3 = *w3p;

    // conv1: y[j] = dot(mean, w1[j,:])  (float4-vectorized, MLP high)
    if (t < HIDE_) {
        const float4* wr = reinterpret_cast<const float4*>(w1 + (size_t)t * C_);
        const float4* ms = reinterpret_cast<const float4*>(mean_s);
        float acc = 0.f;
        #pragma unroll 16
        for (int k = 0; k < C_ / 4; ++k) {
            float4 w = wr[k];
            float4 m = ms[k];
            acc = fmaf(m.x, w.x, acc);
            acc = fmaf(m.y, w.y, acc);
            acc = fmaf(m.z, w.z, acc);
            acc = fmaf(m.w, w.w, acc);
        }
        y_s[t] = acc;
    }
    __syncthreads();

    // softmax over HIDE of (w2 * y)
    float v = (t < HIDE_) ? w2 * y_s[t] : -INFINITY;
    red[t] = v;
    __syncthreads();
    #pragma unroll
    for (int off = 128; off > 0; off >>= 1) {
        if (t < off) red[t] = fmaxf(red[t], red[t + off]);
        __syncthreads();
    }
    float m = red[0];
    __syncthreads();
    float e = (t < HIDE_) ? __expf(v - m) : 0.f;
    red[t] = e;
    __syncthreads();
    #pragma unroll
    for (int off = 128; off > 0; off >>= 1) {
        if (t < off) red[t] += red[t + off];
        __syncthreads();
    }
    float inv_sum = 1.0f / red[0];
    __syncthreads();

    // y2[j] = y[j]*softmax[j] + sum_k y[k]*A2[k,j]; z = relu(w3*y2)
    if (t < HIDE_) {
        float acc = 0.f;
        #pragma unroll 8
        for (int k = 0; k < HIDE_; ++k) acc = fmaf(y_s[k], A2[(size_t)k * HIDE_ + t], acc);
        float y2 = y_s[t] * (e * inv_sum) + acc;
        z_s[t] = fmaxf(w3 * y2, 0.f);
    }
    __syncthreads();

    // conv4 + sigmoid: gate[c] = sigmoid(dot(z, w4[c,:]))
    {
        const float4* wr = reinterpret_cast<const float4*>(w4 + (size_t)t * HIDE_);
        const float4* zs = reinterpret_cast<const float4*>(z_s);
        float acc = 0.f;
        #pragma unroll 16
        for (int k = 0; k < HIDE_ / 4; ++k) {
            float4 w = wr[k];
            float4 z = zs[k];
            acc = fmaf(z.x, w.x, acc);
            acc = fmaf(z.y, w.y, acc);
            acc = fmaf(z.z, w.z, acc);
            acc = fmaf(z.w, w.w, acc);
        }
        g_gate[b * C_ + t] = 1.0f / (1.0f + __expf(-acc));
    }
}

// ---------------- Kernel 3: out = x * gate (one CTA per row, 16 f4/thread) ----------------
__global__ void __launch_bounds__(256) k_scale(const float* __restrict__ x,
                                               float* __restrict__ out) {
    int row = blockIdx.x;
    float g = __ldg(&g_gate[row]);
    const float4* x4 = reinterpret_cast<const float4*>(x) + (size_t)row * HW4_;
    float4* o4 = reinterpret_cast<float4*>(out) + (size_t)row * HW4_;
    #pragma unroll 16
    for (int i = threadIdx.x; i < HW4_; i += 256) {
        float4 v = x4[i];
        v.x *= g; v.y *= g; v.z *= g; v.w *= g;
        o4[i] = v;
    }
}

extern "C" void kernel_launch(void* const* d_in, const int* in_sizes, int n_in,
                              void* d_out, int out_size) {
    const float* x  = (const float*)d_in[0];
    const float* w1 = (const float*)d_in[1];
    const float* w2 = (const float*)d_in[2];
    const float* w3 = (const float*)d_in[3];
    const float* w4 = (const float*)d_in[4];
    const float* A2 = (const float*)d_in[5];
    float* out = (float*)d_out;

    k_reduce<<<ROWS_, 256>>>(x);
    k_gate<<<B_, 256>>>(w1, w2, w3, w4, A2);
    k_scale<<<ROWS_, 256>>>(x, out);
}

// round 4
// speedup vs baseline: 1.1979x; 1.0310x over previous
#include <cuda_runtime.h>
#include <math.h>

// Shapes (fixed by the problem)
#define B_  16
#define C_  256
#define HIDE_ 128
#define HW_ 16384          // 128*128
#define HW4_ 4096          // float4 per row
#define ROWS_ (B_*C_)      // 4096

__device__ float g_mean[ROWS_];
__device__ float g_gate[ROWS_];
__device__ int   g_cnt[B_];      // zero-initialized; self-resetting per launch

// ------- Kernel 1: per-(b,c) mean over H*W; last CTA per batch computes gate -------
__global__ void __launch_bounds__(256) k_reduce_gate(const float* __restrict__ x,
                                                     const float* __restrict__ w1,
                                                     const float* __restrict__ w2p,
                                                     const float* __restrict__ w3p,
                                                     const float* __restrict__ w4,
                                                     const float* __restrict__ A2) {
    int row = blockIdx.x;
    int b = row >> 8;                 // 256 channels per batch
    int t = threadIdx.x;

    // All shared arrays that are float4-cast MUST be 16B aligned.
    __shared__ __align__(16) float mean_s[C_];
    __shared__ __align__(16) float y_s[HIDE_];
    __shared__ __align__(16) float z_s[HIDE_];
    __shared__ __align__(16) float red[256];
    __shared__ float sm[8];
    __shared__ int   last_s;

    // ---- mean over this row ----
    const float4* xr = reinterpret_cast<const float4*>(x) + (size_t)row * HW4_;
    float s = 0.f;
    #pragma unroll 4
    for (int i = t; i < HW4_; i += 256) {
        float4 v = xr[i];
        s += (v.x + v.y) + (v.z + v.w);
    }
    #pragma unroll
    for (int off = 16; off > 0; off >>= 1)
        s += __shfl_down_sync(0xffffffffu, s, off);
    int lane = t & 31, wid = t >> 5;
    if (lane == 0) sm[wid] = s;
    __syncthreads();
    if (t == 0) {
        float tot = 0.f;
        #pragma unroll
        for (int w = 0; w < 8; ++w) tot += sm[w];
        g_mean[row] = tot * (1.0f / (float)HW_);
        __threadfence();
        int old = atomicAdd(&g_cnt[b], 1);
        last_s = (old == C_ - 1);
    }
    __syncthreads();
    if (!last_s) return;

    // ---- last CTA for batch b: compute the 256-wide gate ----
    __threadfence();   // acquire: all g_mean writes for batch b are visible
    mean_s[t] = g_mean[b * C_ + t];
    __syncthreads();

    const float w2 = *w2p;
    const float w3 = *w3p;

    // conv1: y[j] = dot(mean, w1[j,:])
    if (t < HIDE_) {
        const float4* wr = reinterpret_cast<const float4*>(w1 + (size_t)t * C_);
        const float4* ms = reinterpret_cast<const float4*>(mean_s);
        float acc = 0.f;
        #pragma unroll 16
        for (int k = 0; k < C_ / 4; ++k) {
            float4 w = wr[k];
            float4 m = ms[k];
            acc = fmaf(m.x, w.x, acc);
            acc = fmaf(m.y, w.y, acc);
            acc = fmaf(m.z, w.z, acc);
            acc = fmaf(m.w, w.w, acc);
        }
        y_s[t] = acc;
    }
    __syncthreads();

    // softmax over HIDE of (w2 * y)
    float v = (t < HIDE_) ? w2 * y_s[t] : -INFINITY;
    red[t] = v;
    __syncthreads();
    #pragma unroll
    for (int off = 128; off > 0; off >>= 1) {
        if (t < off) red[t] = fmaxf(red[t], red[t + off]);
        __syncthreads();
    }
    float m = red[0];
    __syncthreads();
    float e = (t < HIDE_) ? __expf(v - m) : 0.f;
    red[t] = e;
    __syncthreads();
    #pragma unroll
    for (int off = 128; off > 0; off >>= 1) {
        if (t < off) red[t] += red[t + off];
        __syncthreads();
    }
    float inv_sum = 1.0f / red[0];
    __syncthreads();

    // y2[j] = y[j]*softmax[j] + sum_k y[k]*A2[k,j]; z = relu(w3*y2)
    if (t < HIDE_) {
        float acc = 0.f;
        #pragma unroll 8
        for (int k = 0; k < HIDE_; ++k) acc = fmaf(y_s[k], A2[(size_t)k * HIDE_ + t], acc);
        float y2 = y_s[t] * (e * inv_sum) + acc;
        z_s[t] = fmaxf(w3 * y2, 0.f);
    }
    __syncthreads();

    // conv4 + sigmoid: gate[c] = sigmoid(dot(z, w4[c,:]))
    {
        const float4* wr = reinterpret_cast<const float4*>(w4 + (size_t)t * HIDE_);
        const float4* zs = reinterpret_cast<const float4*>(z_s);
        float acc = 0.f;
        #pragma unroll 16
        for (int k = 0; k < HIDE_ / 4; ++k) {
            float4 w = wr[k];
            float4 z = zs[k];
            acc = fmaf(z.x, w.x, acc);
            acc = fmaf(z.y, w.y, acc);
            acc = fmaf(z.z, w.z, acc);
            acc = fmaf(z.w, w.w, acc);
        }
        g_gate[b * C_ + t] = 1.0f / (1.0f + __expf(-acc));
    }

    // reset counter for next (graph-replayed) launch
    if (t == 0) g_cnt[b] = 0;
}

// ------- Kernel 2: out = x * gate. Reverse row order to hit L2-resident tail of x;
//         streaming loads/stores so out-writes don't evict unread x lines. -------
__global__ void __launch_bounds__(256) k_scale(const float* __restrict__ x,
                                               float* __restrict__ out) {
    int row = (ROWS_ - 1) - blockIdx.x;
    float g = __ldg(&g_gate[row]);
    const float4* x4 = reinterpret_cast<const float4*>(x) + (size_t)row * HW4_;
    float4* o4 = reinterpret_cast<float4*>(out) + (size_t)row * HW4_;
    #pragma unroll 16
    for (int i = threadIdx.x; i < HW4_; i += 256) {
        float4 v = __ldcs(&x4[i]);
        v.x *= g; v.y *= g; v.z *= g; v.w *= g;
        __stcs(&o4[i], v);
    }
}

extern "C" void kernel_launch(void* const* d_in, const int* in_sizes, int n_in,
                              void* d_out, int out_size) {
    const float* x  = (const float*)d_in[0];
    const float* w1 = (const float*)d_in[1];
    const float* w2 = (const float*)d_in[2];
    const float* w3 = (const float*)d_in[3];
    const float* w4 = (const float*)d_in[4];
    const float* A2 = (const float*)d_in[5];
    float* out = (float*)d_out;

    k_reduce_gate<<<ROWS_, 256>>>(x, w1, w2, w3, w4, A2);
    k_scale<<<ROWS_, 256>>>(x, out);
}